// round 2
// baseline (speedup 1.0000x reference)
#include <cuda_runtime.h>
#include <math.h>

// ---------------------------------------------------------------------------
// CausalMoE: B=2, S=2048, H=2048, G=16, GH=8, FFN=8192
// inputs (metadata order):
//  0 hidden_states [2,2048,2048] f32
//  1 P_extract     [2048,16]
//  2 P_route      [16,2048]
//  3 causal_adjacency [16,16]
//  4 W1 [16,17,8]
//  5 b1 [16,8]
//  6 W2 [16,8]
//  7 b2 [16]
//  8 ffn_w1 [2048,8192]
//  9 ffn_b1 [8192]
// 10 ffn_w2 [8192,2048]
// 11 ffn_b2 [2048]
// output [2,2048,2048] f32
// ---------------------------------------------------------------------------

#define ROWS   4096     // B*S
#define H      2048
#define FFN    8192
#define G      16
#define GH     8

// scratch (static device memory: allowed; no runtime allocation)
__device__ float g_modified[(size_t)ROWS * H];      // 32 MB
__device__ float g_ffnh[(size_t)ROWS * FFN];        // 128 MB

__device__ __forceinline__ float gelu_exact(float x) {
    return 0.5f * x * (1.0f + erff(x * 0.7071067811865476f));
}

// ---------------------------------------------------------------------------
// Prologue: one CTA per token row.
//   cv = tanh(hs . P_extract)             [16]
//   pi = cv . Adj                         [16]
//   per-mechanism tiny MLP -> effects     [16]
//   modified = hs + 0.5 * effects . P_route
// ---------------------------------------------------------------------------
__global__ __launch_bounds__(256) void prologue_kernel(
    const float* __restrict__ hs,
    const float* __restrict__ Pe,      // [H,G]
    const float* __restrict__ Pr,      // [G,H]
    const float* __restrict__ Adj,     // [G,G]
    const float* __restrict__ W1,      // [G,G+1,GH]
    const float* __restrict__ b1,      // [G,GH]
    const float* __restrict__ W2,      // [G,GH]
    const float* __restrict__ b2,      // [G]
    float* __restrict__ modified)
{
    const int row  = blockIdx.x;
    const int tid  = threadIdx.x;
    const int lane = tid & 31;
    const int wid  = tid >> 5;         // 0..7
    const float* hrow = hs + (size_t)row * H;

    __shared__ float sh[H];            // 8 KB: hidden row
    __shared__ float wred[8 * G];      // per-warp partials
    __shared__ float cv[G];
    __shared__ float eff[G];

    // stage hidden row
    for (int i = tid; i < H / 4; i += 256)
        ((float4*)sh)[i] = ((const float4*)hrow)[i];
    __syncthreads();

    // cv partial sums: each thread handles strided columns
    float acc[G];
#pragma unroll
    for (int g = 0; g < G; g++) acc[g] = 0.0f;
    for (int c = tid; c < H; c += 256) {
        float x = sh[c];
        const float* pe = Pe + c * G;
#pragma unroll
        for (int g = 0; g < G; g++) acc[g] = fmaf(x, pe[g], acc[g]);
    }
    // warp-level reduce each of the 16 sums
#pragma unroll
    for (int g = 0; g < G; g++) {
#pragma unroll
        for (int s = 16; s > 0; s >>= 1)
            acc[g] += __shfl_xor_sync(0xffffffffu, acc[g], s);
    }
    if (lane < G) wred[wid * G + lane] = acc[lane]; // lane g holds sum g (all lanes equal)
    __syncthreads();

    if (tid < G) {
        float s = 0.0f;
#pragma unroll
        for (int w = 0; w < 8; w++) s += wred[w * G + tid];
        cv[tid] = tanhf(s);
    }
    __syncthreads();

    // mechanisms: one thread per mechanism (threads 0..15)
    if (tid < G) {
        const int m = tid;
        float pi = 0.0f;
#pragma unroll
        for (int g = 0; g < G; g++) pi = fmaf(cv[g], Adj[g * G + m], pi);

        float e = b2[m];
#pragma unroll
        for (int j = 0; j < GH; j++) {
            float hh = b1[m * GH + j];
#pragma unroll
            for (int v = 0; v < G; v++)
                hh = fmaf(cv[v], W1[((size_t)m * (G + 1) + v) * GH + j], hh);
            hh = fmaf(pi, W1[((size_t)m * (G + 1) + G) * GH + j], hh);
            hh = gelu_exact(hh);
            e = fmaf(hh, W2[m * GH + j], e);
        }
        eff[m] = 0.5f * e;   // fold INTERVENTION_STRENGTH
    }
    __syncthreads();

    // modified = hs + sum_g eff[g] * P_route[g, :]
    float le[G];
#pragma unroll
    for (int g = 0; g < G; g++) le[g] = eff[g];
    for (int c = tid; c < H; c += 256) {
        float v = sh[c];
#pragma unroll
        for (int g = 0; g < G; g++) v = fmaf(le[g], Pr[g * H + c], v);
        modified[(size_t)row * H + c] = v;
    }
}

// ---------------------------------------------------------------------------
// Double-buffered fp32 SGEMM: C[M,N] = A[M,K] * B[K,N] + bias (+ opt GELU)
// BM=BN=128, BK=16, 256 threads, 8x8 per thread. All dims divide tiles here.
// Next K-tile is prefetched to registers during compute, stored to the other
// smem buffer, one __syncthreads per iteration.
// ---------------------------------------------------------------------------
template <bool DO_GELU>
__global__ __launch_bounds__(256) void sgemm_kernel(
    const float* __restrict__ A,
    const float* __restrict__ B,
    const float* __restrict__ bias,
    float* __restrict__ C,
    int M, int N, int K)
{
    constexpr int BM = 128, BN = 128, BK = 16;

    __shared__ float As[2][BK][BM];   // K-major for broadcast reads
    __shared__ float Bs[2][BK][BN];

    const int tid = threadIdx.x;
    const int bx = blockIdx.x;     // N tile
    const int by = blockIdx.y;     // M tile

    const float* Ab = A + (size_t)by * BM * K;
    const float* Bb = B + (size_t)bx * BN;

    // A-tile: 128 rows x 16 cols = 512 float4; 2 per thread
    const int aRow  = tid >> 2;          // 0..63
    const int aCol4 = tid & 3;           // 0..3 (float4 along K)
    // B-tile: 16 rows x 128 cols = 512 float4; 2 per thread
    const int bRow  = tid >> 5;          // 0..7
    const int bCol4 = tid & 31;          // 0..31

    const int tr = tid >> 4;             // 0..15
    const int tc = tid & 15;             // 0..15

    float acc[8][8];
#pragma unroll
    for (int i = 0; i < 8; i++)
#pragma unroll
        for (int j = 0; j < 8; j++) acc[i][j] = 0.0f;

    // ---- prime buffer 0
    float4 pa[2], pb[2];
#pragma unroll
    for (int t = 0; t < 2; t++) {
        pa[t] = *(const float4*)(Ab + (size_t)(aRow + t * 64) * K + aCol4 * 4);
        pb[t] = *(const float4*)(Bb + (size_t)(bRow + t * 8) * N + bCol4 * 4);
    }
#pragma unroll
    for (int t = 0; t < 2; t++) {
        int r = aRow + t * 64;
        As[0][aCol4 * 4 + 0][r] = pa[t].x;
        As[0][aCol4 * 4 + 1][r] = pa[t].y;
        As[0][aCol4 * 4 + 2][r] = pa[t].z;
        As[0][aCol4 * 4 + 3][r] = pa[t].w;
        *(float4*)(&Bs[0][bRow + t * 8][bCol4 * 4]) = pb[t];
    }
    __syncthreads();

    const int nIter = K / BK;
    int buf = 0;
    for (int it = 0; it < nIter; it++) {
        // prefetch next tile to registers (no smem hazard)
        if (it + 1 < nIter) {
            int k0 = (it + 1) * BK;
#pragma unroll
            for (int t = 0; t < 2; t++) {
                pa[t] = *(const float4*)(Ab + (size_t)(aRow + t * 64) * K + k0 + aCol4 * 4);
                pb[t] = *(const float4*)(Bb + (size_t)(k0 + bRow + t * 8) * N + bCol4 * 4);
            }
        }

        // compute on current buffer
#pragma unroll
        for (int k = 0; k < BK; k++) {
            float ra[8], rb[8];
            *(float4*)(ra)     = *(const float4*)(&As[buf][k][tr * 8]);
            *(float4*)(ra + 4) = *(const float4*)(&As[buf][k][tr * 8 + 4]);
            *(float4*)(rb)     = *(const float4*)(&Bs[buf][k][tc * 8]);
            *(float4*)(rb + 4) = *(const float4*)(&Bs[buf][k][tc * 8 + 4]);
#pragma unroll
            for (int i = 0; i < 8; i++)
#pragma unroll
                for (int j = 0; j < 8; j++)
                    acc[i][j] = fmaf(ra[i], rb[j], acc[i][j]);
        }

        // store prefetched tile into the other buffer
        if (it + 1 < nIter) {
            int nb = buf ^ 1;
            __syncthreads();   // ensure everyone finished reading nb from 2 iters ago
#pragma unroll
            for (int t = 0; t < 2; t++) {
                int r = aRow + t * 64;
                As[nb][aCol4 * 4 + 0][r] = pa[t].x;
                As[nb][aCol4 * 4 + 1][r] = pa[t].y;
                As[nb][aCol4 * 4 + 2][r] = pa[t].z;
                As[nb][aCol4 * 4 + 3][r] = pa[t].w;
                *(float4*)(&Bs[nb][bRow + t * 8][bCol4 * 4]) = pb[t];
            }
            __syncthreads();
            buf = nb;
        }
    }

    // epilogue
#pragma unroll
    for (int i = 0; i < 8; i++) {
        const size_t r = (size_t)by * BM + tr * 8 + i;
#pragma unroll
        for (int j = 0; j < 8; j += 4) {
            const int c = bx * BN + tc * 8 + j;
            float4 v;
            v.x = acc[i][j + 0] + bias[c + 0];
            v.y = acc[i][j + 1] + bias[c + 1];
            v.z = acc[i][j + 2] + bias[c + 2];
            v.w = acc[i][j + 3] + bias[c + 3];
            if (DO_GELU) {
                v.x = gelu_exact(v.x);
                v.y = gelu_exact(v.y);
                v.z = gelu_exact(v.z);
                v.w = gelu_exact(v.w);
            }
            *(float4*)(C + r * N + c) = v;
        }
    }
}

// ---------------------------------------------------------------------------
extern "C" void kernel_launch(void* const* d_in, const int* in_sizes, int n_in,
                              void* d_out, int out_size)
{
    const float* hs   = (const float*)d_in[0];
    const float* Pe   = (const float*)d_in[1];
    const float* Pr   = (const float*)d_in[2];
    const float* Adj  = (const float*)d_in[3];
    const float* W1   = (const float*)d_in[4];
    const float* b1   = (const float*)d_in[5];
    const float* W2   = (const float*)d_in[6];
    const float* b2   = (const float*)d_in[7];
    const float* fw1  = (const float*)d_in[8];
    const float* fb1  = (const float*)d_in[9];
    const float* fw2  = (const float*)d_in[10];
    const float* fb2  = (const float*)d_in[11];
    float* out = (float*)d_out;

    float* modified;
    float* ffnh;
    cudaGetSymbolAddress((void**)&modified, g_modified);
    cudaGetSymbolAddress((void**)&ffnh, g_ffnh);

    // 1) fused prologue
    prologue_kernel<<<ROWS, 256>>>(hs, Pe, Pr, Adj, W1, b1, W2, b2, modified);

    // 2) FFN GEMM1 + GELU: [4096,2048] x [2048,8192]
    {
        dim3 grid(FFN / 128, ROWS / 128);
        sgemm_kernel<true><<<grid, 256>>>(modified, fw1, fb1, ffnh, ROWS, FFN, H);
    }

    // 3) FFN GEMM2: [4096,8192] x [8192,2048]
    {
        dim3 grid(H / 128, ROWS / 128);
        sgemm_kernel<false><<<grid, 256>>>(ffnh, fw2, fb2, out, ROWS, H, FFN);
    }
}

// round 3
// speedup vs baseline: 3.2167x; 3.2167x over previous
#include <cuda_runtime.h>
#include <math.h>
#include <stdint.h>

// ---------------------------------------------------------------------------
// CausalMoE: B=2, S=2048, H=2048, G=16, GH=8, FFN=8192
// Round 3: tf32 tensor-core GEMMs (mma.sync.m16n8k8) + vectorized prologue.
// ---------------------------------------------------------------------------

#define ROWS   4096     // B*S
#define H      2048
#define FFN    8192
#define G      16
#define GH     8

// scratch (static device memory: allowed; no runtime allocation)
__device__ float g_modified[(size_t)ROWS * H];      // 32 MB
__device__ float g_ffnh[(size_t)ROWS * FFN];        // 128 MB

__device__ __forceinline__ float gelu_exact(float x) {
    return 0.5f * x * (1.0f + erff(x * 0.7071067811865476f));
}

__device__ __forceinline__ uint32_t f2tf32(float x) {
    uint32_t u;
    asm("cvt.rna.tf32.f32 %0, %1;" : "=r"(u) : "f"(x));
    return u;
}

__device__ __forceinline__ void mma_tf32(float c[4],
                                         uint32_t a0, uint32_t a1, uint32_t a2, uint32_t a3,
                                         uint32_t b0, uint32_t b1) {
    asm volatile(
        "mma.sync.aligned.m16n8k8.row.col.f32.tf32.tf32.f32 "
        "{%0,%1,%2,%3}, {%4,%5,%6,%7}, {%8,%9}, {%0,%1,%2,%3};\n"
        : "+f"(c[0]), "+f"(c[1]), "+f"(c[2]), "+f"(c[3])
        : "r"(a0), "r"(a1), "r"(a2), "r"(a3), "r"(b0), "r"(b1));
}

// ---------------------------------------------------------------------------
// Prologue: one CTA per token row, fully vectorized loads.
// ---------------------------------------------------------------------------
__global__ __launch_bounds__(256) void prologue_kernel(
    const float* __restrict__ hs,
    const float* __restrict__ Pe,      // [H,G]
    const float* __restrict__ Pr,      // [G,H]
    const float* __restrict__ Adj,     // [G,G]
    const float* __restrict__ W1,      // [G,G+1,GH]
    const float* __restrict__ b1,      // [G,GH]
    const float* __restrict__ W2,      // [G,GH]
    const float* __restrict__ b2,      // [G]
    float* __restrict__ modified)
{
    const int row  = blockIdx.x;
    const int tid  = threadIdx.x;
    const int lane = tid & 31;
    const int wid  = tid >> 5;         // 0..7
    const float* hrow = hs + (size_t)row * H;

    __shared__ float sh[H];            // 8 KB
    __shared__ float wred[8 * G];
    __shared__ float cv[G];
    __shared__ float eff[G];

    for (int i = tid; i < H / 4; i += 256)
        ((float4*)sh)[i] = ((const float4*)hrow)[i];
    __syncthreads();

    // cv partial sums; Pe rows loaded as float4
    float acc[G];
#pragma unroll
    for (int g = 0; g < G; g++) acc[g] = 0.0f;
    for (int i = tid; i < H / 4; i += 256) {
        float4 x4 = ((const float4*)sh)[i];
        const float* xe = (const float*)&x4;
        int c = i * 4;
#pragma unroll
        for (int e = 0; e < 4; e++) {
            float x = xe[e];
            const float4* pe4 = (const float4*)(Pe + (size_t)(c + e) * G);
#pragma unroll
            for (int q = 0; q < 4; q++) {
                float4 p = pe4[q];
                acc[q * 4 + 0] = fmaf(x, p.x, acc[q * 4 + 0]);
                acc[q * 4 + 1] = fmaf(x, p.y, acc[q * 4 + 1]);
                acc[q * 4 + 2] = fmaf(x, p.z, acc[q * 4 + 2]);
                acc[q * 4 + 3] = fmaf(x, p.w, acc[q * 4 + 3]);
            }
        }
    }
#pragma unroll
    for (int g = 0; g < G; g++) {
#pragma unroll
        for (int s = 16; s > 0; s >>= 1)
            acc[g] += __shfl_xor_sync(0xffffffffu, acc[g], s);
    }
    if (lane < G) wred[wid * G + lane] = acc[lane];
    __syncthreads();

    if (tid < G) {
        float s = 0.0f;
#pragma unroll
        for (int w = 0; w < 8; w++) s += wred[w * G + tid];
        cv[tid] = tanhf(s);
    }
    __syncthreads();

    if (tid < G) {
        const int m = tid;
        float pi = 0.0f;
#pragma unroll
        for (int g = 0; g < G; g++) pi = fmaf(cv[g], Adj[g * G + m], pi);

        float e = b2[m];
#pragma unroll
        for (int j = 0; j < GH; j++) {
            float hh = b1[m * GH + j];
#pragma unroll
            for (int v = 0; v < G; v++)
                hh = fmaf(cv[v], W1[((size_t)m * (G + 1) + v) * GH + j], hh);
            hh = fmaf(pi, W1[((size_t)m * (G + 1) + G) * GH + j], hh);
            hh = gelu_exact(hh);
            e = fmaf(hh, W2[m * GH + j], e);
        }
        eff[m] = 0.5f * e;   // fold INTERVENTION_STRENGTH
    }
    __syncthreads();

    float le[G];
#pragma unroll
    for (int g = 0; g < G; g++) le[g] = eff[g];
    for (int i = tid; i < H / 4; i += 256) {
        float4 v = ((const float4*)sh)[i];
#pragma unroll
        for (int g = 0; g < G; g++) {
            float4 p = ((const float4*)(Pr + (size_t)g * H))[i];
            v.x = fmaf(le[g], p.x, v.x);
            v.y = fmaf(le[g], p.y, v.y);
            v.z = fmaf(le[g], p.z, v.z);
            v.w = fmaf(le[g], p.w, v.w);
        }
        ((float4*)(modified + (size_t)row * H))[i] = v;
    }
}

// ---------------------------------------------------------------------------
// tf32 tensor-core GEMM: C[M,N] = A[M,K]*B[K,N] + bias (+opt GELU)
// BM=BN=128, BK=16, 256 threads (8 warps, 4x2), warp tile 32x64,
// mma.m16n8k8.tf32, double-buffered smem with register prefetch.
// ---------------------------------------------------------------------------
template <bool DO_GELU>
__global__ __launch_bounds__(256) void tf32gemm_kernel(
    const float* __restrict__ A,
    const float* __restrict__ B,
    const float* __restrict__ bias,
    float* __restrict__ C,
    int M, int N, int K)
{
    constexpr int BM = 128, BN = 128, BK = 16;
    constexpr int APAD = 4;    // stride 20: bank = (4r + c) % 32 -> conflict-free frag reads
    constexpr int BPAD = 8;    // stride 136: bank = (8k + n) % 32 -> conflict-free frag reads

    __shared__ uint32_t As[2][BM][BK + APAD];   // 2 * 10240 B
    __shared__ uint32_t Bs[2][BK][BN + BPAD];   // 2 * 8704 B

    const int tid  = threadIdx.x;
    const int lane = tid & 31;
    const int wid  = tid >> 5;
    const int bx = blockIdx.x;     // N tile
    const int by = blockIdx.y;     // M tile

    const int warpM = (wid & 3) * 32;   // 4 warps along M
    const int warpN = (wid >> 2) * 64;  // 2 warps along N

    const float* Ab = A + (size_t)by * BM * K;
    const float* Bb = B + (size_t)bx * BN;

    // A tile load: 128 rows x 16 k = 512 float4, 2/thread
    const int aRow  = tid >> 2;          // 0..63 (+64)
    const int aCol4 = tid & 3;           // float4 along K
    // B tile load: 16 rows x 128 cols = 512 float4, 2/thread
    const int bRow  = tid >> 5;          // 0..7 (+8)
    const int bCol4 = tid & 31;

    float acc[2][8][4];
#pragma unroll
    for (int mt = 0; mt < 2; mt++)
#pragma unroll
        for (int nt = 0; nt < 8; nt++)
#pragma unroll
            for (int q = 0; q < 4; q++) acc[mt][nt][q] = 0.0f;

    float4 pa[2], pb[2];

    // ---- prime buffer 0
#pragma unroll
    for (int t = 0; t < 2; t++) {
        pa[t] = *(const float4*)(Ab + (size_t)(aRow + t * 64) * K + aCol4 * 4);
        pb[t] = *(const float4*)(Bb + (size_t)(bRow + t * 8) * N + bCol4 * 4);
    }
#pragma unroll
    for (int t = 0; t < 2; t++) {
        int r = aRow + t * 64;
        As[0][r][aCol4 * 4 + 0] = f2tf32(pa[t].x);
        As[0][r][aCol4 * 4 + 1] = f2tf32(pa[t].y);
        As[0][r][aCol4 * 4 + 2] = f2tf32(pa[t].z);
        As[0][r][aCol4 * 4 + 3] = f2tf32(pa[t].w);
        uint32_t* bp = &Bs[0][bRow + t * 8][bCol4 * 4];
        bp[0] = f2tf32(pb[t].x);
        bp[1] = f2tf32(pb[t].y);
        bp[2] = f2tf32(pb[t].z);
        bp[3] = f2tf32(pb[t].w);
    }
    __syncthreads();

    const int nIter = K / BK;
    int buf = 0;
    for (int it = 0; it < nIter; it++) {
        if (it + 1 < nIter) {
            int k0 = (it + 1) * BK;
#pragma unroll
            for (int t = 0; t < 2; t++) {
                pa[t] = *(const float4*)(Ab + (size_t)(aRow + t * 64) * K + k0 + aCol4 * 4);
                pb[t] = *(const float4*)(Bb + (size_t)(k0 + bRow + t * 8) * N + bCol4 * 4);
            }
        }

        // compute: 2 k-steps of 8
#pragma unroll
        for (int ks = 0; ks < 2; ks++) {
            const int kk = ks * 8;
            uint32_t af[2][4], bf[8][2];
            const int kc = kk + (lane & 3);
            const int rg = lane >> 2;
#pragma unroll
            for (int mt = 0; mt < 2; mt++) {
                int r = warpM + mt * 16 + rg;
                af[mt][0] = As[buf][r][kc];
                af[mt][1] = As[buf][r + 8][kc];
                af[mt][2] = As[buf][r][kc + 4];
                af[mt][3] = As[buf][r + 8][kc + 4];
            }
#pragma unroll
            for (int nt = 0; nt < 8; nt++) {
                int n = warpN + nt * 8 + rg;
                bf[nt][0] = Bs[buf][kc][n];
                bf[nt][1] = Bs[buf][kc + 4][n];
            }
#pragma unroll
            for (int mt = 0; mt < 2; mt++)
#pragma unroll
                for (int nt = 0; nt < 8; nt++)
                    mma_tf32(acc[mt][nt], af[mt][0], af[mt][1], af[mt][2], af[mt][3],
                             bf[nt][0], bf[nt][1]);
        }

        if (it + 1 < nIter) {
            int nb = buf ^ 1;
            __syncthreads();
#pragma unroll
            for (int t = 0; t < 2; t++) {
                int r = aRow + t * 64;
                As[nb][r][aCol4 * 4 + 0] = f2tf32(pa[t].x);
                As[nb][r][aCol4 * 4 + 1] = f2tf32(pa[t].y);
                As[nb][r][aCol4 * 4 + 2] = f2tf32(pa[t].z);
                As[nb][r][aCol4 * 4 + 3] = f2tf32(pa[t].w);
                uint32_t* bp = &Bs[nb][bRow + t * 8][bCol4 * 4];
                bp[0] = f2tf32(pb[t].x);
                bp[1] = f2tf32(pb[t].y);
                bp[2] = f2tf32(pb[t].z);
                bp[3] = f2tf32(pb[t].w);
            }
            __syncthreads();
            buf = nb;
        }
    }

    // epilogue: c0,c1 at (r, 2c), (r, 2c+1); c2,c3 at (r+8, ...)
    const int rg = lane >> 2;
    const int cg = (lane & 3) * 2;
#pragma unroll
    for (int mt = 0; mt < 2; mt++) {
        const size_t r0 = (size_t)by * BM + warpM + mt * 16 + rg;
        const size_t r1 = r0 + 8;
#pragma unroll
        for (int nt = 0; nt < 8; nt++) {
            const int c = bx * BN + warpN + nt * 8 + cg;
            float2 v0, v1;
            v0.x = acc[mt][nt][0] + bias[c];
            v0.y = acc[mt][nt][1] + bias[c + 1];
            v1.x = acc[mt][nt][2] + bias[c];
            v1.y = acc[mt][nt][3] + bias[c + 1];
            if (DO_GELU) {
                v0.x = gelu_exact(v0.x); v0.y = gelu_exact(v0.y);
                v1.x = gelu_exact(v1.x); v1.y = gelu_exact(v1.y);
            }
            *(float2*)(C + r0 * N + c) = v0;
            *(float2*)(C + r1 * N + c) = v1;
        }
    }
}

// ---------------------------------------------------------------------------
extern "C" void kernel_launch(void* const* d_in, const int* in_sizes, int n_in,
                              void* d_out, int out_size)
{
    const float* hs   = (const float*)d_in[0];
    const float* Pe   = (const float*)d_in[1];
    const float* Pr   = (const float*)d_in[2];
    const float* Adj  = (const float*)d_in[3];
    const float* W1   = (const float*)d_in[4];
    const float* b1   = (const float*)d_in[5];
    const float* W2   = (const float*)d_in[6];
    const float* b2   = (const float*)d_in[7];
    const float* fw1  = (const float*)d_in[8];
    const float* fb1  = (const float*)d_in[9];
    const float* fw2  = (const float*)d_in[10];
    const float* fb2  = (const float*)d_in[11];
    float* out = (float*)d_out;

    float* modified;
    float* ffnh;
    cudaGetSymbolAddress((void**)&modified, g_modified);
    cudaGetSymbolAddress((void**)&ffnh, g_ffnh);

    // 1) fused prologue
    prologue_kernel<<<ROWS, 256>>>(hs, Pe, Pr, Adj, W1, b1, W2, b2, modified);

    // 2) FFN GEMM1 + GELU: [4096,2048] x [2048,8192]
    {
        dim3 grid(FFN / 128, ROWS / 128);
        tf32gemm_kernel<true><<<grid, 256>>>(modified, fw1, fb1, ffnh, ROWS, FFN, H);
    }

    // 3) FFN GEMM2: [4096,8192] x [8192,2048]
    {
        dim3 grid(H / 128, ROWS / 128);
        tf32gemm_kernel<false><<<grid, 256>>>(ffnh, fw2, fb2, out, ROWS, H, FFN);
    }
}